// round 1
// baseline (speedup 1.0000x reference)
#include <cuda_runtime.h>

// ---------------------------------------------------------------------------
// GAT 3-layer forward. Structure:
//   CSR build (dst-grouped) once per launch:  zero / hist / scan / scatter
//   Layer l:  GEMM (X @ Wl -> H)  ->  att dots (a_s, a_d)  ->  aggregate
//   Layers 0/1 epilogue: +bias, ELU, BN(eval).  Layer 2: +bias, log_softmax.
// All scratch in __device__ globals (no allocation).
// ---------------------------------------------------------------------------

#define MAXN 10240
#define MAXE 340000

__device__ float g_H[MAXN * 256];      // GEMM output (pre-aggregation features)
__device__ float g_X[MAXN * 256];      // aggregated/activated features
__device__ float g_as[MAXN * 4];
__device__ float g_ad[MAXN * 4];
__device__ int   g_cnt[MAXN];
__device__ int   g_off[MAXN + 1];
__device__ int   g_wp[MAXN];
__device__ int   g_csr_src[MAXE];

// ---------------------------------------------------------------------------
// GEMM: C[M,N] = A[M,K] @ B[K,N], fp32, 64x64 tile, 4x4 per thread, BK=16.
// ---------------------------------------------------------------------------
__global__ void gemm64(const float* __restrict__ A, const float* __restrict__ B,
                       float* __restrict__ C, int M, int N, int K)
{
    __shared__ float As[16][68];
    __shared__ float Bs[16][68];
    int tid = threadIdx.x;          // 256
    int tx = tid & 15, ty = tid >> 4;
    int row0 = blockIdx.x * 64, col0 = blockIdx.y * 64;
    float acc[4][4] = {};

    for (int k0 = 0; k0 < K; k0 += 16) {
        #pragma unroll
        for (int i = 0; i < 4; i++) {
            int lin = tid + i * 256;
            int kk = lin & 15, r = lin >> 4;
            int gr = row0 + r;
            As[kk][r] = (gr < M) ? A[(size_t)gr * K + k0 + kk] : 0.f;
        }
        #pragma unroll
        for (int i = 0; i < 4; i++) {
            int lin = tid + i * 256;
            int c = lin & 63, kk = lin >> 6;
            Bs[kk][c] = B[(size_t)(k0 + kk) * N + col0 + c];
        }
        __syncthreads();
        #pragma unroll
        for (int kk = 0; kk < 16; kk++) {
            float4 a4 = *reinterpret_cast<const float4*>(&As[kk][ty * 4]);
            float4 b4 = *reinterpret_cast<const float4*>(&Bs[kk][tx * 4]);
            float av[4] = {a4.x, a4.y, a4.z, a4.w};
            float bv[4] = {b4.x, b4.y, b4.z, b4.w};
            #pragma unroll
            for (int i = 0; i < 4; i++)
                #pragma unroll
                for (int j = 0; j < 4; j++)
                    acc[i][j] += av[i] * bv[j];
        }
        __syncthreads();
    }
    #pragma unroll
    for (int i = 0; i < 4; i++) {
        int gr = row0 + ty * 4 + i;
        if (gr < M) {
            #pragma unroll
            for (int j = 0; j < 4; j++)
                C[(size_t)gr * N + col0 + tx * 4 + j] = acc[i][j];
        }
    }
}

// ---------------------------------------------------------------------------
// Attention dot products: a_s[n,h] = sum_c H[n,h,c]*att_src[h,c], same for dst.
// blockDim = 32*heads, one warp per head.
// ---------------------------------------------------------------------------
__global__ void att_dots(const float* __restrict__ H, const float* __restrict__ asw,
                         const float* __restrict__ adw, float* __restrict__ as_o,
                         float* __restrict__ ad_o, int heads, int C)
{
    int n = blockIdx.x;
    int lane = threadIdx.x & 31;
    int h = threadIdx.x >> 5;
    int HC = heads * C;
    float ss = 0.f, sd = 0.f;
    for (int c = lane; c < C; c += 32) {
        float v = H[(size_t)n * HC + h * C + c];
        ss += v * asw[h * C + c];
        sd += v * adw[h * C + c];
    }
    #pragma unroll
    for (int o = 16; o; o >>= 1) {
        ss += __shfl_xor_sync(0xffffffffu, ss, o);
        sd += __shfl_xor_sync(0xffffffffu, sd, o);
    }
    if (lane == 0) { as_o[n * heads + h] = ss; ad_o[n * heads + h] = sd; }
}

// ---------------------------------------------------------------------------
// CSR build
// ---------------------------------------------------------------------------
__global__ void zero_cnt(int N)
{
    int i = blockIdx.x * blockDim.x + threadIdx.x;
    if (i < N) g_cnt[i] = 0;
}

__global__ void hist_k(const int* __restrict__ ei, int E, int Etot)
{
    int e = blockIdx.x * blockDim.x + threadIdx.x;
    if (e >= Etot) return;
    int d = (e < E) ? ei[E + e] : (e - E);   // self-loops appended
    atomicAdd(&g_cnt[d], 1);
}

// single block, 1024 threads, exclusive scan of g_cnt into g_off (and g_wp)
__global__ void scan_k(int N, int Etot)
{
    __shared__ int wsum[32];
    int tid = threadIdx.x;
    const int PER = 12;                 // covers N up to 12288
    int base = tid * PER;
    int loc[PER];
    int s = 0;
    #pragma unroll
    for (int i = 0; i < PER; i++) {
        int idx = base + i;
        int v = (idx < N) ? g_cnt[idx] : 0;
        loc[i] = s; s += v;
    }
    int lane = tid & 31, wid = tid >> 5;
    int x = s;
    #pragma unroll
    for (int o = 1; o < 32; o <<= 1) {
        int y = __shfl_up_sync(0xffffffffu, x, o);
        if (lane >= o) x += y;
    }
    if (lane == 31) wsum[wid] = x;
    __syncthreads();
    if (wid == 0) {
        int w = wsum[lane];
        #pragma unroll
        for (int o = 1; o < 32; o <<= 1) {
            int y = __shfl_up_sync(0xffffffffu, w, o);
            if (lane >= o) w += y;
        }
        wsum[lane] = w;
    }
    __syncthreads();
    int excl = x - s + (wid ? wsum[wid - 1] : 0);
    #pragma unroll
    for (int i = 0; i < PER; i++) {
        int idx = base + i;
        if (idx < N) { int v = excl + loc[i]; g_off[idx] = v; g_wp[idx] = v; }
    }
    if (tid == 0) g_off[N] = Etot;
}

__global__ void scatter_k(const int* __restrict__ ei, int E, int Etot)
{
    int e = blockIdx.x * blockDim.x + threadIdx.x;
    if (e >= Etot) return;
    int sIdx, d;
    if (e < E) { sIdx = ei[e]; d = ei[E + e]; } else { sIdx = d = e - E; }
    int pos = atomicAdd(&g_wp[d], 1);
    g_csr_src[pos] = sIdx;
}

// ---------------------------------------------------------------------------
// Aggregation, heads=4, C=64, concat -> 256 channels.
// One block (128 threads) per dst node. float2 per thread (channels 2t,2t+1).
// Softmax stats 2-pass, then chunked weights in SMEM + coalesced H gathers.
// Epilogue: bias, ELU, BN(eval).
// ---------------------------------------------------------------------------
__global__ void agg4(const float* __restrict__ H, const float* __restrict__ as,
                     const float* __restrict__ ad, const float* __restrict__ bias,
                     const float* __restrict__ gam, const float* __restrict__ bet,
                     const float* __restrict__ mu, const float* __restrict__ var,
                     float* __restrict__ out)
{
    int n = blockIdx.x;
    int tid = threadIdx.x;          // 128
    int beg = g_off[n];
    int deg = g_off[n + 1] - beg;
    __shared__ float red[128];
    __shared__ float w_sh[128];     // [32 edges][4 heads], idx = e*4+h
    __shared__ int   src_sh[32];
    __shared__ float m_s[4], iv_s[4];

    int ch = tid >> 2;              // chunk edge slot 0..31
    int hh = tid & 3;               // chunk head
    float adv = ad[n * 4 + hh];

    // pass 1: max logit per head
    float mx = -1e30f;
    for (int b0 = 0; b0 < deg; b0 += 32) {
        int i = b0 + ch;
        if (i < deg) {
            int s = g_csr_src[beg + i];
            float l = as[s * 4 + hh] + adv;
            l = (l > 0.f) ? l : 0.2f * l;
            mx = fmaxf(mx, l);
        }
    }
    red[tid] = mx; __syncthreads();
    #pragma unroll
    for (int s = 64; s >= 4; s >>= 1) {
        if (tid < s) red[tid] = fmaxf(red[tid], red[tid + s]);
        __syncthreads();
    }
    if (tid < 4) m_s[tid] = red[tid];
    __syncthreads();
    float mh = m_s[hh];

    // pass 2: sum of exp
    float sm = 0.f;
    for (int b0 = 0; b0 < deg; b0 += 32) {
        int i = b0 + ch;
        if (i < deg) {
            int s = g_csr_src[beg + i];
            float l = as[s * 4 + hh] + adv;
            l = (l > 0.f) ? l : 0.2f * l;
            sm += __expf(l - mh);
        }
    }
    red[tid] = sm; __syncthreads();
    #pragma unroll
    for (int s = 64; s >= 4; s >>= 1) {
        if (tid < s) red[tid] += red[tid + s];
        __syncthreads();
    }
    if (tid < 4) iv_s[tid] = 1.f / (red[tid] + 1e-16f);
    __syncthreads();

    // pass 3: weighted gather
    int my_h = tid >> 5;
    int c = tid * 2;
    float accx = 0.f, accy = 0.f;
    float mh2 = m_s[hh], iv2 = iv_s[hh];
    for (int b0 = 0; b0 < deg; b0 += 32) {
        int i = b0 + ch;
        __syncthreads();
        if (i < deg) {
            int s = g_csr_src[beg + i];
            float l = as[s * 4 + hh] + adv;
            l = (l > 0.f) ? l : 0.2f * l;
            w_sh[ch * 4 + hh] = __expf(l - mh2) * iv2;
            if (hh == 0) src_sh[ch] = s;
        }
        __syncthreads();
        int lim = min(32, deg - b0);
        for (int j = 0; j < lim; j++) {
            int s = src_sh[j];
            float w = w_sh[j * 4 + my_h];                 // broadcast within warp
            float2 hv = *reinterpret_cast<const float2*>(H + (size_t)s * 256 + c);
            accx += w * hv.x;
            accy += w * hv.y;
        }
    }

    // epilogue: bias, ELU, BN eval
    float v0 = accx + bias[c];
    float v1 = accy + bias[c + 1];
    v0 = (v0 > 0.f) ? v0 : (__expf(v0) - 1.f);
    v1 = (v1 > 0.f) ? v1 : (__expf(v1) - 1.f);
    float sc0 = gam[c]     * rsqrtf(var[c]     + 1e-5f);
    float sc1 = gam[c + 1] * rsqrtf(var[c + 1] + 1e-5f);
    v0 = sc0 * (v0 - mu[c])     + bet[c];
    v1 = sc1 * (v1 - mu[c + 1]) + bet[c + 1];
    out[(size_t)n * 256 + c]     = v0;
    out[(size_t)n * 256 + c + 1] = v1;
}

// ---------------------------------------------------------------------------
// Final layer: heads=1, C=64, concat=False (mean over 1 head = identity),
// +bias, log_softmax over the 64 channels. One block (64 threads) per node.
// ---------------------------------------------------------------------------
__global__ void agg_fin(const float* __restrict__ H, const float* __restrict__ as,
                        const float* __restrict__ ad, const float* __restrict__ bias,
                        float* __restrict__ out)
{
    int n = blockIdx.x, tid = threadIdx.x;  // 64
    int beg = g_off[n];
    int deg = g_off[n + 1] - beg;
    __shared__ float red[64];
    __shared__ float w_sh[64];
    __shared__ int   src_sh[64];
    __shared__ float sh_m, sh_iv;
    float adv = ad[n];

    float mx = -1e30f;
    for (int i = tid; i < deg; i += 64) {
        int s = g_csr_src[beg + i];
        float l = as[s] + adv; l = (l > 0.f) ? l : 0.2f * l;
        mx = fmaxf(mx, l);
    }
    red[tid] = mx; __syncthreads();
    #pragma unroll
    for (int s = 32; s >= 1; s >>= 1) {
        if (tid < s) red[tid] = fmaxf(red[tid], red[tid + s]);
        __syncthreads();
    }
    if (tid == 0) sh_m = red[0];
    __syncthreads();
    float m = sh_m;

    float sm = 0.f;
    for (int i = tid; i < deg; i += 64) {
        int s = g_csr_src[beg + i];
        float l = as[s] + adv; l = (l > 0.f) ? l : 0.2f * l;
        sm += __expf(l - m);
    }
    red[tid] = sm; __syncthreads();
    #pragma unroll
    for (int s = 32; s >= 1; s >>= 1) {
        if (tid < s) red[tid] += red[tid + s];
        __syncthreads();
    }
    if (tid == 0) sh_iv = 1.f / (red[0] + 1e-16f);
    __syncthreads();
    float iv = sh_iv;

    float acc = 0.f;
    for (int b0 = 0; b0 < deg; b0 += 64) {
        int i = b0 + tid;
        __syncthreads();
        if (i < deg) {
            int s = g_csr_src[beg + i];
            float l = as[s] + adv; l = (l > 0.f) ? l : 0.2f * l;
            w_sh[tid] = __expf(l - m) * iv;
            src_sh[tid] = s;
        }
        __syncthreads();
        int lim = min(64, deg - b0);
        for (int j = 0; j < lim; j++)
            acc += w_sh[j] * H[(size_t)src_sh[j] * 64 + tid];
    }

    float z = acc + bias[tid];
    red[tid] = z; __syncthreads();
    #pragma unroll
    for (int s = 32; s >= 1; s >>= 1) {
        if (tid < s) red[tid] = fmaxf(red[tid], red[tid + s]);
        __syncthreads();
    }
    float zm = red[0]; __syncthreads();
    red[tid] = __expf(z - zm); __syncthreads();
    #pragma unroll
    for (int s = 32; s >= 1; s >>= 1) {
        if (tid < s) red[tid] += red[tid + s];
        __syncthreads();
    }
    float lse = zm + logf(red[0]);
    out[(size_t)n * 64 + tid] = z - lse;
}

// ---------------------------------------------------------------------------
extern "C" void kernel_launch(void* const* d_in, const int* in_sizes, int n_in,
                              void* d_out, int out_size)
{
    const float* x    = (const float*)d_in[0];
    const int*   ei   = (const int*)  d_in[1];
    const float* W0   = (const float*)d_in[2];
    const float* as0w = (const float*)d_in[3];
    const float* ad0w = (const float*)d_in[4];
    const float* b0   = (const float*)d_in[5];
    const float* gm0  = (const float*)d_in[6];
    const float* be0  = (const float*)d_in[7];
    const float* mu0  = (const float*)d_in[8];
    const float* vr0  = (const float*)d_in[9];
    const float* W1   = (const float*)d_in[10];
    const float* as1w = (const float*)d_in[11];
    const float* ad1w = (const float*)d_in[12];
    const float* b1   = (const float*)d_in[13];
    const float* gm1  = (const float*)d_in[14];
    const float* be1  = (const float*)d_in[15];
    const float* mu1  = (const float*)d_in[16];
    const float* vr1  = (const float*)d_in[17];
    const float* W2   = (const float*)d_in[18];
    const float* as2w = (const float*)d_in[19];
    const float* ad2w = (const float*)d_in[20];
    const float* b2   = (const float*)d_in[21];

    int N = in_sizes[0] / 128;      // 10000
    int E = in_sizes[1] / 2;        // 320000
    int Etot = E + N;

    float *H, *X, *AS, *AD;
    cudaGetSymbolAddress((void**)&H,  g_H);
    cudaGetSymbolAddress((void**)&X,  g_X);
    cudaGetSymbolAddress((void**)&AS, g_as);
    cudaGetSymbolAddress((void**)&AD, g_ad);

    // CSR build (shared by all 3 layers)
    zero_cnt<<<(N + 255) / 256, 256>>>(N);
    hist_k<<<(Etot + 255) / 256, 256>>>(ei, E, Etot);
    scan_k<<<1, 1024>>>(N, Etot);
    scatter_k<<<(Etot + 255) / 256, 256>>>(ei, E, Etot);

    // layer 0: 128 -> 4x64 concat
    gemm64<<<dim3((N + 63) / 64, 4), 256>>>(x, W0, H, N, 256, 128);
    att_dots<<<N, 128>>>(H, as0w, ad0w, AS, AD, 4, 64);
    agg4<<<N, 128>>>(H, AS, AD, b0, gm0, be0, mu0, vr0, X);

    // layer 1: 256 -> 4x64 concat
    gemm64<<<dim3((N + 63) / 64, 4), 256>>>(X, W1, H, N, 256, 256);
    att_dots<<<N, 128>>>(H, as1w, ad1w, AS, AD, 4, 64);
    agg4<<<N, 128>>>(H, AS, AD, b1, gm1, be1, mu1, vr1, X);

    // layer 2: 256 -> 64, heads=1, + log_softmax
    gemm64<<<dim3((N + 63) / 64, 1), 256>>>(X, W2, H, N, 64, 256);
    att_dots<<<N, 32>>>(H, as2w, ad2w, AS, AD, 1, 64);
    agg_fin<<<N, 64>>>(H, AS, AD, b2, (float*)d_out);
}